// round 10
// baseline (speedup 1.0000x reference)
#include <cuda_runtime.h>
#include <cstdint>

// Problem constants: B=8, N=500000, H=W=512, HALF_CENTOR=true
#define BB    8
#define NPTS  500000
#define HH    512
#define WW    512
#define NCELL (BB * HH * WW)   // 2,097,152 cells
#define NPAIR (NPTS / 2)       // 250,000 point-pairs per batch

// Separate scratch arrays (same-sector min+cnt pairs serialize in one LTS
// atomic bank — round-2 evidence). Zero is the sentinel for both; the
// finalize phase restores zeros, so every call / graph replay starts clean.
__device__ unsigned int g_min[NCELL];   // 8 MB: max of ~enc_f(cost), 0 = empty
__device__ unsigned int g_cnt[NCELL];   // 8 MB: point count, 0 = empty
__device__ unsigned int g_bar;          // monotone grid-barrier ticket counter

// Order-preserving float -> uint (monotone increasing).
__device__ __forceinline__ unsigned int enc_f(float f) {
    unsigned int u = __float_as_uint(f);
    return (u & 0x80000000u) ? ~u : (u | 0x80000000u);
}
__device__ __forceinline__ float dec_f(unsigned int u) {
    return __uint_as_float((u & 0x80000000u) ? (u & 0x7FFFFFFFu) : ~u);
}

// Deadlock-safe software grid barrier (all blocks guaranteed resident by the
// launch shape). Monotone ticket counter survives graph replays: each block
// waits for the end of its own "round" of nb arrivals.
__device__ __forceinline__ void grid_barrier(unsigned int nb) {
    __threadfence();                       // release: my REDs visible
    __syncthreads();
    if (threadIdx.x == 0) {
        unsigned int tick   = atomicAdd(&g_bar, 1u);
        unsigned int target = (tick / nb + 1u) * nb;
        unsigned int v;
        do {
            asm volatile("ld.acquire.gpu.b32 %0, [%1];"
                         : "=r"(v) : "l"(&g_bar) : "memory");
            if (v >= target) break;
            __nanosleep(100);
        } while (true);
    }
    __syncthreads();
    __threadfence();                       // acquire: others' REDs visible
}

// ---------------------------------------------------------------------------
// Fused persistent kernel: scatter (grid-stride, 2 pts/iter) -> grid barrier
// -> finalize (grid-stride, 8 cells/iter, loads up-front, plain stores).
// ---------------------------------------------------------------------------
__global__ void __launch_bounds__(1024, 2)
k_fused(const float4* __restrict__ points2,   // [B*NPAIR] (x0,y0,x1,y1)
        const float2* __restrict__ costs2,    // [B*NPAIR]
        float* __restrict__ out_cost,
        float* __restrict__ out_mask,
        const float* __restrict__ default_cost,
        unsigned int nblocks) {
    const int gsz  = gridDim.x * blockDim.x;
    const int gtid = blockIdx.x * blockDim.x + threadIdx.x;

    // ---- Phase 1: scatter ----
    #pragma unroll 1
    for (int b = 0; b < BB; b++) {
        const float4* pb = points2 + (size_t)b * NPAIR;
        const float2* cb = costs2  + (size_t)b * NPAIR;
        const int base = b * HH * WW;
        #pragma unroll 1
        for (int t = gtid; t < NPAIR; t += gsz) {
            float4 p = pb[t];
            float2 c = cb[t];
            int ix0 = (int)floorf(p.x + 0.5f);
            int iy0 = (int)floorf(p.y + 0.5f);
            int ix1 = (int)floorf(p.z + 0.5f);
            int iy1 = (int)floorf(p.w + 0.5f);
            if ((unsigned)ix0 < (unsigned)WW && (unsigned)iy0 < (unsigned)HH) {
                int cell = base + iy0 * WW + ix0;
                atomicMax(&g_min[cell], ~enc_f(c.x));  // RED, result unused
                atomicAdd(&g_cnt[cell], 1u);           // RED
            }
            if ((unsigned)ix1 < (unsigned)WW && (unsigned)iy1 < (unsigned)HH) {
                int cell = base + iy1 * WW + ix1;
                atomicMax(&g_min[cell], ~enc_f(c.y));
                atomicAdd(&g_cnt[cell], 1u);
            }
        }
    }

    // ---- Grid-wide barrier: all REDs complete & visible ----
    grid_barrier(nblocks);

    // ---- Phase 2: finalize (8 cells per iteration) ----
    const float d = __ldg(default_cost);
    const uint4* mv = reinterpret_cast<const uint4*>(g_min);
    const uint4* cv = reinterpret_cast<const uint4*>(g_cnt);
    uint4* mw = reinterpret_cast<uint4*>(g_min);
    uint4* cw = reinterpret_cast<uint4*>(g_cnt);
    float4* oc = reinterpret_cast<float4*>(out_cost);
    float4* om = reinterpret_cast<float4*>(out_mask);
    const uint4 z = make_uint4(0u, 0u, 0u, 0u);

    #pragma unroll 1
    for (int i = gtid; i < NCELL / 8; i += gsz) {
        // issue all 4 loads up-front (MLP = 4)
        uint4 m0 = mv[2 * i + 0];
        uint4 m1 = mv[2 * i + 1];
        uint4 c0 = cv[2 * i + 0];
        uint4 c1 = cv[2 * i + 1];

        float4 q0, q1, k0, k1;
        q0.x = c0.x ? dec_f(~m0.x) : d;  k0.x = (float)((int)c0.x - 1);
        q0.y = c0.y ? dec_f(~m0.y) : d;  k0.y = (float)((int)c0.y - 1);
        q0.z = c0.z ? dec_f(~m0.z) : d;  k0.z = (float)((int)c0.z - 1);
        q0.w = c0.w ? dec_f(~m0.w) : d;  k0.w = (float)((int)c0.w - 1);
        q1.x = c1.x ? dec_f(~m1.x) : d;  k1.x = (float)((int)c1.x - 1);
        q1.y = c1.y ? dec_f(~m1.y) : d;  k1.y = (float)((int)c1.y - 1);
        q1.z = c1.z ? dec_f(~m1.z) : d;  k1.z = (float)((int)c1.z - 1);
        q1.w = c1.w ? dec_f(~m1.w) : d;  k1.w = (float)((int)c1.w - 1);

        oc[2 * i + 0] = q0;
        oc[2 * i + 1] = q1;
        if (om) {
            om[2 * i + 0] = k0;
            om[2 * i + 1] = k1;
        }
        // restore zero sentinels (L2-resident; next call starts clean)
        mw[2 * i + 0] = z;
        mw[2 * i + 1] = z;
        cw[2 * i + 0] = z;
        cw[2 * i + 1] = z;
    }
}

// ---------------------------------------------------------------------------
// Launcher. Inputs: points[B,N,2] f32, costs[B,N] f32, default_cost f32,
// height i32, width i32. Output: [cost | mask] as f32.
// ---------------------------------------------------------------------------
extern "C" void kernel_launch(void* const* d_in, const int* in_sizes, int n_in,
                              void* d_out, int out_size) {
    const float4* points2      = (const float4*)d_in[0];
    const float2* costs2       = (const float2*)d_in[1];
    const float*  default_cost = (const float*)d_in[2];

    float* out_cost = (float*)d_out;
    float* out_mask = (out_size >= 2 * NCELL) ? out_cost + NCELL : nullptr;

    int sms = 148;
    cudaDeviceGetAttribute(&sms, cudaDevAttrMultiProcessorCount, 0);

    k_fused<<<sms, 1024>>>(points2, costs2, out_cost, out_mask,
                           default_cost, (unsigned int)sms);
}

// round 11
// speedup vs baseline: 1.6662x; 1.6662x over previous
#include <cuda_runtime.h>
#include <cstdint>

// Problem constants: B=8, N=500000, H=W=512, HALF_CENTOR=true
#define BB    8
#define NPTS  500000
#define HH    512
#define WW    512
#define NCELL (BB * HH * WW)   // 2,097,152 cells
#define NPAIR (NPTS / 2)       // 250,000 point-pairs per batch

// Separate scratch arrays (interleaved (min,cnt) serialized in one LTS atomic
// bank — round-2 evidence). Zero is the sentinel for both (module-load zero
// init); k_final restores zeros after reading, so every kernel_launch call /
// graph replay sees zeros on entry.
//   g_min[cell] = max over points of mkey = ~enc_f(cost); larger mkey ==
//                 smaller cost, every float encodes to mkey >= 1.
//   g_cnt[cell] = number of points that hit the cell.
__device__ unsigned int g_min[NCELL];   // 8 MB
__device__ unsigned int g_cnt[NCELL];   // 8 MB

// Order-preserving float -> uint (monotone increasing).
__device__ __forceinline__ unsigned int enc_f(float f) {
    unsigned int u = __float_as_uint(f);
    return (u & 0x80000000u) ? ~u : (u | 0x80000000u);
}
__device__ __forceinline__ float dec_f(unsigned int u) {
    return __uint_as_float((u & 0x80000000u) ? (u & 0x7FFFFFFFu) : ~u);
}

// ---------------------------------------------------------------------------
// Scatter: 2 points per thread, massive grid (1M threads -> full TLP),
// UNCONDITIONAL fire-and-forget REDs. One float4 + one float2 load per pair.
// grid = (ceil(NPAIR/256), B).
// ---------------------------------------------------------------------------
__global__ void k_scatter(const float4* __restrict__ points2,  // [B*NPAIR] (x0,y0,x1,y1)
                          const float2* __restrict__ costs2) { // [B*NPAIR]
    int t = blockIdx.x * blockDim.x + threadIdx.x;
    int b = blockIdx.y;
    if (t >= NPAIR) return;
    int gi = b * NPAIR + t;
    float4 p = points2[gi];
    float2 c = costs2[gi];
    const int base = b * HH * WW;

    int ix0 = (int)floorf(p.x + 0.5f);
    int iy0 = (int)floorf(p.y + 0.5f);
    int ix1 = (int)floorf(p.z + 0.5f);
    int iy1 = (int)floorf(p.w + 0.5f);

    if ((unsigned)ix0 < (unsigned)WW && (unsigned)iy0 < (unsigned)HH) {
        int cell = base + iy0 * WW + ix0;
        atomicMax(&g_min[cell], ~enc_f(c.x));  // RED (result unused)
        atomicAdd(&g_cnt[cell], 1u);           // RED
    }
    if ((unsigned)ix1 < (unsigned)WW && (unsigned)iy1 < (unsigned)HH) {
        int cell = base + iy1 * WW + ix1;
        atomicMax(&g_min[cell], ~enc_f(c.y));
        atomicAdd(&g_cnt[cell], 1u);
    }
}

// ---------------------------------------------------------------------------
// Finalize: 8 cells per thread, all 4 uint4 loads issued up-front (MLP=4),
// PLAIN stores (write-back; __stwt was the round-5 regressor). Decodes min or
// default, emits mask = count-1, restores zero sentinels.
// ---------------------------------------------------------------------------
__global__ void k_final(float* __restrict__ out_cost,
                        float* __restrict__ out_mask,
                        const float* __restrict__ default_cost) {
    int i = blockIdx.x * blockDim.x + threadIdx.x;   // group of 8 cells
    if (i >= NCELL / 8) return;

    const uint4* mv = reinterpret_cast<const uint4*>(g_min);
    const uint4* cv = reinterpret_cast<const uint4*>(g_cnt);
    uint4 m0 = mv[2 * i + 0];
    uint4 m1 = mv[2 * i + 1];
    uint4 c0 = cv[2 * i + 0];
    uint4 c1 = cv[2 * i + 1];

    const float d = __ldg(default_cost);
    float4 q0, q1, k0, k1;
    q0.x = c0.x ? dec_f(~m0.x) : d;  k0.x = (float)((int)c0.x - 1);
    q0.y = c0.y ? dec_f(~m0.y) : d;  k0.y = (float)((int)c0.y - 1);
    q0.z = c0.z ? dec_f(~m0.z) : d;  k0.z = (float)((int)c0.z - 1);
    q0.w = c0.w ? dec_f(~m0.w) : d;  k0.w = (float)((int)c0.w - 1);
    q1.x = c1.x ? dec_f(~m1.x) : d;  k1.x = (float)((int)c1.x - 1);
    q1.y = c1.y ? dec_f(~m1.y) : d;  k1.y = (float)((int)c1.y - 1);
    q1.z = c1.z ? dec_f(~m1.z) : d;  k1.z = (float)((int)c1.z - 1);
    q1.w = c1.w ? dec_f(~m1.w) : d;  k1.w = (float)((int)c1.w - 1);

    float4* oc = reinterpret_cast<float4*>(out_cost);
    oc[2 * i + 0] = q0;
    oc[2 * i + 1] = q1;
    if (out_mask) {
        float4* om = reinterpret_cast<float4*>(out_mask);
        om[2 * i + 0] = k0;
        om[2 * i + 1] = k1;
    }

    // restore zero sentinels (L2-resident stores; next call starts clean)
    uint4 z = make_uint4(0u, 0u, 0u, 0u);
    reinterpret_cast<uint4*>(g_min)[2 * i + 0] = z;
    reinterpret_cast<uint4*>(g_min)[2 * i + 1] = z;
    reinterpret_cast<uint4*>(g_cnt)[2 * i + 0] = z;
    reinterpret_cast<uint4*>(g_cnt)[2 * i + 1] = z;
}

// ---------------------------------------------------------------------------
// Launcher. Inputs: points[B,N,2] f32, costs[B,N] f32, default_cost f32,
// height i32, width i32. Output: [cost | mask] as f32.
// ---------------------------------------------------------------------------
extern "C" void kernel_launch(void* const* d_in, const int* in_sizes, int n_in,
                              void* d_out, int out_size) {
    const float4* points2      = (const float4*)d_in[0];
    const float2* costs2       = (const float2*)d_in[1];
    const float*  default_cost = (const float*)d_in[2];

    float* out_cost = (float*)d_out;
    float* out_mask = (out_size >= 2 * NCELL) ? out_cost + NCELL : nullptr;

    const int T = 256;
    dim3 sg((NPAIR + T - 1) / T, BB);
    k_scatter<<<sg, T>>>(points2, costs2);

    k_final<<<(NCELL / 8 + T - 1) / T, T>>>(out_cost, out_mask, default_cost);
}